// round 10
// baseline (speedup 1.0000x reference)
#include <cuda_runtime.h>
#include <cstdint>

#define NUM_ENT 64
#define DIM 4
#define HALF 128
#define BATCH 512
#define IHALF 32
#define THREADS 256
#define TANH3_A (-0.328685f)

typedef unsigned long long u64;
typedef ulonglong2 u64x2;

__device__ __forceinline__ u64 pk(float lo, float hi) {
    u64 r; asm("mov.b64 %0, {%1, %2};" : "=l"(r) : "f"(lo), "f"(hi)); return r;
}
__device__ __forceinline__ u64 fma2(u64 a, u64 b, u64 c) {
    u64 r; asm("fma.rn.f32x2 %0, %1, %2, %3;" : "=l"(r) : "l"(a), "l"(b), "l"(c)); return r;
}
__device__ __forceinline__ u64 add2(u64 a, u64 b) {
    u64 r; asm("add.rn.f32x2 %0, %1, %2;" : "=l"(r) : "l"(a), "l"(b)); return r;
}
__device__ __forceinline__ u64 sub2(u64 a, u64 b) {
    u64 r; asm("sub.rn.f32x2 %0, %1, %2;" : "=l"(r) : "l"(a), "l"(b)); return r;
}
__device__ __forceinline__ u64 mul2(u64 a, u64 b) {
    u64 r; asm("mul.rn.f32x2 %0, %1, %2;" : "=l"(r) : "l"(a), "l"(b)); return r;
}

// E-moment monomial tables: 34 = 4 singles + 10 pairs + 20 triples (row 4 of sEt = 1.0)
__device__ const int EM_A[34] = {0,1,2,3, 0,0,0,0,1,1,1,2,2,3,
    0,0,0,0,0,0,0,0,0,0, 1,1,1,1,1,1, 2,2,2, 3};
__device__ const int EM_B[34] = {4,4,4,4, 0,1,2,3,1,2,3,2,3,3,
    0,0,0,0,1,1,1,2,2,3, 1,1,1,2,2,3, 2,2,3, 3};
__device__ const int EM_C[34] = {4,4,4,4, 4,4,4,4,4,4,4,4,4,4,
    0,1,2,3,1,2,3,2,3,3, 1,2,3,2,3,3, 2,3,3, 3};
__device__ const float EM_CF[34] = {1,1,1,1, 1,1,1,1,1,1,1,1,1,1,
    1,3,3,3,3,6,6,3,6,3, 1,3,3,3,6,3, 1,3,3, 1};

__global__ void __launch_bounds__(THREADS, 3) enc_kernel(
    const float* __restrict__ ctx, const float* __restrict__ Wp,
    const float* __restrict__ bp, const float* __restrict__ Wr,
    const float* __restrict__ br, float* __restrict__ out)
{
    __shared__ float sEt[5][66];                       // E^T rows 0-3, row 4 = ones
    __shared__ __align__(16) u64 sEdup[NUM_ENT][4];    // pk(e,e)
    __shared__ __align__(16) u64 sWr2[5][64];
    __shared__ __align__(16) u64 sWp2[4][64];
    __shared__ u64 sBr2[64], sBp2[64];
    __shared__ u64 sEm[34];
    __shared__ __align__(16) u64 sIM[IHALF][22];       // per-i D moments (dup)
    __shared__ __align__(16) u64 sHPt[26][64];         // per-hp coeffs, TRANSPOSED

    const int tid = threadIdx.x;
    const int b = blockIdx.x >> 1;
    const int ibase = (blockIdx.x & 1) * IHALF;

    // ---- Phase 0: stage inputs ----
    {
        const float ev = ctx[tid * BATCH + b];         // tid = j*4 + d
        sEt[tid & 3][tid >> 2] = ev;
        sEdup[tid >> 2][tid & 3] = pk(ev, ev);
        for (int k = tid; k < 5 * 64; k += THREADS) {
            const int d = k >> 6, hp = k & 63;
            sWr2[d][hp] = pk(Wr[d * HALF + 2 * hp], Wr[d * HALF + 2 * hp + 1]);
        }
        {
            const int d = tid >> 6, hp = tid & 63;
            sWp2[d][hp] = pk(Wp[d * HALF + 2 * hp], Wp[d * HALF + 2 * hp + 1]);
        }
        if (tid < 64) {
            sBr2[tid] = pk(br[2 * tid], br[2 * tid + 1]);
            sBp2[tid] = pk(bp[2 * tid], bp[2 * tid + 1]);
            sEt[4][tid] = 1.0f;
        }
    }
    __syncthreads();

    // ================= REGION A (between sync0 and sync1) =================

    // A1: per-i D moments (8 threads per i, shfl-reduce)
    {
        const int il = tid >> 3;
        const int i = ibase + il;
        const int jb = (tid & 7) * 8;
        const float exi = sEt[0][i], eyi = sEt[1][i];
        float m[21];
#pragma unroll
        for (int k = 0; k < 21; k++) m[k] = 0.0f;
#pragma unroll
        for (int jj = 0; jj < 8; jj++) {
            const int j = jb + jj;
            const float e0 = sEt[0][j], e1 = sEt[1][j], e2 = sEt[2][j], e3 = sEt[3][j];
            const float dx = exi - e0, dy = eyi - e1;
            float d2 = fmaf(dx, dx, dy * dy);
            float d;
            if (i == j) { d = 1.0f; d2 = 1.0f; } else { d = sqrtf(d2); }
            const float d3 = d2 * d;
            const float de0 = d * e0, de1 = d * e1, de2 = d * e2, de3 = d * e3;
            m[0] += de0; m[1] += de1; m[2] += de2; m[3] += de3;             // D*E
            m[4] = fmaf(d2, e0, m[4]); m[5] = fmaf(d2, e1, m[5]);           // D^2*E
            m[6] = fmaf(d2, e2, m[6]); m[7] = fmaf(d2, e3, m[7]);
            m[8]  = fmaf(de0, e0, m[8]);  m[9]  = fmaf(de0, e1, m[9]);      // D*G
            m[10] = fmaf(de0, e2, m[10]); m[11] = fmaf(de0, e3, m[11]);
            m[12] = fmaf(de1, e1, m[12]); m[13] = fmaf(de1, e2, m[13]);
            m[14] = fmaf(de1, e3, m[14]); m[15] = fmaf(de2, e2, m[15]);
            m[16] = fmaf(de2, e3, m[16]); m[17] = fmaf(de3, e3, m[17]);
            m[18] += d; m[19] += d2; m[20] += d3;                           // D1,D2s,D3
        }
#pragma unroll
        for (int s = 1; s < 8; s <<= 1)
#pragma unroll
            for (int k = 0; k < 21; k++)
                m[k] += __shfl_xor_sync(0xffffffffu, m[k], s);
        if ((tid & 7) == 0) {
#pragma unroll
            for (int k = 0; k < 21; k++) sIM[il][k] = pk(m[k], m[k]);
            sIM[il][21] = 0;
        }
    }

    // A2: prop_emb (all threads; needs only sync0 data)
    {
        const int hp = tid & 63, ig = tid >> 6;
        const u64 wp0 = sWp2[0][hp], wp1 = sWp2[1][hp],
                  wp2v = sWp2[2][hp], wp3v = sWp2[3][hp];
        const u64 bp2v = sBp2[hp];
        const u64 ONE = pk(1.0f, 1.0f);
        const u64 T7 = pk(-0.053968254f, -0.053968254f);
        const u64 T5 = pk(0.13333334f, 0.13333334f);
        const u64 T3 = pk(-0.33333334f, -0.33333334f);
        float* outB = out + (size_t)b * NUM_ENT * 2 * HALF;
#pragma unroll 2
        for (int k = 0; k < 8; k++) {
            const int i = ibase + ig * 8 + k;
            const u64x2 eA = *reinterpret_cast<const u64x2*>(&sEdup[i][0]);
            const u64x2 eB = *reinterpret_cast<const u64x2*>(&sEdup[i][2]);
            u64 pp = fma2(eA.x, wp0, bp2v);
            pp = fma2(eA.y, wp1, pp);
            pp = fma2(eB.x, wp2v, pp);
            pp = fma2(eB.y, wp3v, pp);
            const u64 t = mul2(pp, pp);
            u64 u = fma2(t, T7, T5);
            u = fma2(t, u, T3);
            u = fma2(t, u, ONE);
            reinterpret_cast<u64*>(outB + (size_t)i * (2 * HALF))[hp] = mul2(pp, u);
        }
    }

    // A3: E-moment monomial sums, 136 threads (4 j-chunks of 16, shfl-reduce)
    if (tid < 136) {
        const int m = tid >> 2, c = tid & 3;
        const unsigned mask = (tid < 128) ? 0xffffffffu : 0xffu;
        const int a = EM_A[m], bb = EM_B[m], cc = EM_C[m];
        float s = 0.0f;
        const int j0 = c * 16;
#pragma unroll 4
        for (int jj = 0; jj < 16; jj++) {
            const int j = j0 + jj;
            s = fmaf(sEt[a][j] * sEt[bb][j], sEt[cc][j], s);
        }
        s += __shfl_xor_sync(mask, s, 1);
        s += __shfl_xor_sync(mask, s, 2);
        if (c == 0) { s *= EM_CF[m]; sEm[m] = pk(s, s); }
    }

    // A4: sEm-INDEPENDENT per-hp coefficients (threads 192..255)
    if (tid >= 192) {
        const int hp = tid - 192;
        const u64 w0 = sWr2[0][hp], w1 = sWr2[1][hp],
                  w2v = sWr2[2][hp], w3v = sWr2[3][hp], w = sWr2[4][hp];
        const u64 wq[4] = { w0, w1, w2v, w3v };
        u64 pr[10];
        pr[0] = mul2(w0, w0); pr[1] = mul2(w0, w1); pr[2] = mul2(w0, w2v);
        pr[3] = mul2(w0, w3v); pr[4] = mul2(w1, w1); pr[5] = mul2(w1, w2v);
        pr[6] = mul2(w1, w3v); pr[7] = mul2(w2v, w2v); pr[8] = mul2(w2v, w3v);
        pr[9] = mul2(w3v, w3v);
        u64 W2[10];
#pragma unroll
        for (int g = 0; g < 10; g++) W2[g] = pr[g];
        W2[1] = add2(W2[1], W2[1]); W2[2] = add2(W2[2], W2[2]);
        W2[3] = add2(W2[3], W2[3]); W2[5] = add2(W2[5], W2[5]);
        W2[6] = add2(W2[6], W2[6]); W2[8] = add2(W2[8], W2[8]);
        const u64 C3c = pk(3.0f, 3.0f);
        const u64 c3w = mul2(w, C3c);
        const u64 c3w2 = mul2(c3w, w);
        const u64 w3c = mul2(mul2(w, w), w);
        const u64 m6w = mul2(w, pk(-6.0f, -6.0f));
        const u64 nc3w2 = sub2(0ull, c3w2);
        sHPt[2][hp] = c3w;
        sHPt[4][hp] = c3w2;
        sHPt[6][hp] = w3c;
#pragma unroll
        for (int d = 0; d < 4; d++) sHPt[8 + d][hp] = mul2(wq[d], m6w);     // u
#pragma unroll
        for (int d = 0; d < 4; d++) sHPt[12 + d][hp] = mul2(wq[d], nc3w2);  // t
#pragma unroll
        for (int g = 0; g < 10; g++) sHPt[16 + g][hp] = mul2(W2[g], c3w);   // v
    }
    __syncthreads();

    // ---- Phase W: sEm-DEPENDENT coefficients, 128 threads ----
    if (tid < 64) {
        const int hp = tid;
        const u64 w0 = sWr2[0][hp], w1 = sWr2[1][hp],
                  w2v = sWr2[2][hp], w3v = sWr2[3][hp], w = sWr2[4][hp];
        u64 S1 = mul2(sEm[0], w0);
        S1 = fma2(sEm[1], w1, S1);
        S1 = fma2(sEm[2], w2v, S1);
        S1 = fma2(sEm[3], w3v, S1);
        u64 pr[10];
        pr[0] = mul2(w0, w0); pr[1] = mul2(w0, w1); pr[2] = mul2(w0, w2v);
        pr[3] = mul2(w0, w3v); pr[4] = mul2(w1, w1); pr[5] = mul2(w1, w2v);
        pr[6] = mul2(w1, w3v); pr[7] = mul2(w2v, w2v); pr[8] = mul2(w2v, w3v);
        pr[9] = mul2(w3v, w3v);
        u64 W2[10];
#pragma unroll
        for (int g = 0; g < 10; g++) W2[g] = pr[g];
        W2[1] = add2(W2[1], W2[1]); W2[2] = add2(W2[2], W2[2]);
        W2[3] = add2(W2[3], W2[3]); W2[5] = add2(W2[5], W2[5]);
        W2[6] = add2(W2[6], W2[6]); W2[8] = add2(W2[8], W2[8]);
        u64 S2 = mul2(sEm[4], W2[0]);
#pragma unroll
        for (int g = 1; g < 10; g++) S2 = fma2(sEm[4 + g], W2[g], S2);
        const u64 z = add2(w, sBr2[hp]);
        sHPt[0][hp] = sub2(sub2(0ull, S1), z);          // Lc
        sHPt[1][hp] = mul2(S1, pk(-3.0f, -3.0f));       // n3S1
        sHPt[3][hp] = mul2(S2, pk(3.0f, 3.0f));         // p3S2
    } else if (tid < 128) {
        const int hp = tid - 64;
        const u64 w0 = sWr2[0][hp], w1 = sWr2[1][hp],
                  w2v = sWr2[2][hp], w3v = sWr2[3][hp], w = sWr2[4][hp];
        const u64 wq[4] = { w0, w1, w2v, w3v };
        u64 pr[10];
        pr[0] = mul2(w0, w0); pr[1] = mul2(w0, w1); pr[2] = mul2(w0, w2v);
        pr[3] = mul2(w0, w3v); pr[4] = mul2(w1, w1); pr[5] = mul2(w1, w2v);
        pr[6] = mul2(w1, w3v); pr[7] = mul2(w2v, w2v); pr[8] = mul2(w2v, w3v);
        pr[9] = mul2(w3v, w3v);
        constexpr int P3[20] = {0,0,0,0,1,1,1,2,2,3,4,4,4,5,5,6,7,7,8,9};
        constexpr int C3i[20] = {0,1,2,3,1,2,3,2,3,3,1,2,3,2,3,3,2,3,3,3};
        u64 S3 = 0;
#pragma unroll
        for (int m3 = 0; m3 < 20; m3++)
            S3 = fma2(sEm[14 + m3], mul2(pr[P3[m3]], wq[C3i[m3]]), S3);
        const u64 z = add2(w, sBr2[hp]);
        const u64 z3 = mul2(z, mul2(z, z));
        sHPt[5][hp] = sub2(sub2(0ull, S3), z3);         // K0
    }
    __syncthreads();

    // ---- Epilogue: thread = (hp, ig); 8 i each ----
    {
        const int hp = tid & 63;
        const int ig = tid >> 6;

        const u64 wr0 = sWr2[0][hp], wr1 = sWr2[1][hp],
                  wr2v = sWr2[2][hp], wr3v = sWr2[3][hp], wr4 = sWr2[4][hp];
        const u64 br2v = sBr2[hp];
        const u64 A2 = pk(TANH3_A, TANH3_A);
        const u64 C64 = pk(64.0f, 64.0f);

        // conflict-free strided coeff loads (transposed layout)
        const u64 Lc   = sHPt[0][hp], n3S1 = sHPt[1][hp], c3w  = sHPt[2][hp];
        const u64 p3S2 = sHPt[3][hp], c3w2 = sHPt[4][hp], K0   = sHPt[5][hp];
        const u64 w3c  = sHPt[6][hp];
        const u64 u0 = sHPt[8][hp],  u1 = sHPt[9][hp],
                  u2 = sHPt[10][hp], u3 = sHPt[11][hp];
        const u64 t0 = sHPt[12][hp], t1 = sHPt[13][hp],
                  t2 = sHPt[14][hp], t3 = sHPt[15][hp];

        float* outB = out + (size_t)b * NUM_ENT * 2 * HALF;

#pragma unroll 2
        for (int k = 0; k < 8; k++) {
            const int il = ig * 8 + k;
            const int i = ibase + il;
            const u64x2 eA = *reinterpret_cast<const u64x2*>(&sEdup[i][0]);
            const u64x2 eB = *reinterpret_cast<const u64x2*>(&sEdup[i][2]);

            u64 p = mul2(eA.x, wr0);
            p = fma2(eA.y, wr1, p);
            p = fma2(eB.x, wr2v, p);
            p = fma2(eB.y, wr3v, p);
            const u64 q = add2(p, br2v);

            const u64x2* M = reinterpret_cast<const u64x2*>(sIM[il]);  // broadcast
            const u64x2 de01 = M[0], de23 = M[1], f01 = M[2], f23 = M[3];
            const u64x2 g01 = M[4], g23 = M[5], g45 = M[6], g67 = M[7], g89 = M[8];
            const u64x2 dd01 = M[9], dd2_ = M[10];   // D1,D2s | D3,pad

            const u64 C2 = fma2(dd01.x, c3w, n3S1);

            u64 C1 = fma2(de01.x, u0, p3S2);
            C1 = fma2(de01.y, u1, C1);
            C1 = fma2(de23.x, u2, C1);
            C1 = fma2(de23.y, u3, C1);
            C1 = fma2(dd01.y, c3w2, C1);

            u64 C0 = fma2(g01.x, sHPt[16][hp], K0);
            C0 = fma2(g01.y, sHPt[17][hp], C0);
            C0 = fma2(g23.x, sHPt[18][hp], C0);
            C0 = fma2(g23.y, sHPt[19][hp], C0);
            C0 = fma2(g45.x, sHPt[20][hp], C0);
            C0 = fma2(g45.y, sHPt[21][hp], C0);
            C0 = fma2(g67.x, sHPt[22][hp], C0);
            C0 = fma2(g67.y, sHPt[23][hp], C0);
            C0 = fma2(g89.x, sHPt[24][hp], C0);
            C0 = fma2(g89.y, sHPt[25][hp], C0);
            C0 = fma2(f01.x, t0, C0);
            C0 = fma2(f01.y, t1, C0);
            C0 = fma2(f23.x, t2, C0);
            C0 = fma2(f23.y, t3, C0);
            C0 = fma2(dd2_.x, w3c, C0);

            u64 cub = fma2(C64, q, C2);
            cub = fma2(cub, q, C1);
            cub = fma2(cub, q, C0);

            u64 lin = fma2(C64, q, Lc);
            lin = fma2(dd01.x, wr4, lin);

            const u64 res = fma2(A2, cub, lin);
            reinterpret_cast<u64*>(outB + (size_t)i * (2 * HALF))[64 + hp] = res;
        }
    }
}

extern "C" void kernel_launch(void* const* d_in, const int* in_sizes, int n_in,
                              void* d_out, int out_size) {
    const float* ctx = (const float*)d_in[0];
    const float* Wp  = (const float*)d_in[1];
    const float* bp  = (const float*)d_in[2];
    const float* Wr  = (const float*)d_in[3];
    const float* br  = (const float*)d_in[4];
    float* out = (float*)d_out;
    (void)in_sizes; (void)n_in; (void)out_size;
    enc_kernel<<<BATCH * 2, THREADS>>>(ctx, Wp, bp, Wr, br, out);
}

// round 11
// speedup vs baseline: 2.0706x; 2.0706x over previous
#include <cuda_runtime.h>
#include <cstdint>

#define NUM_ENT 64
#define DIM 4
#define HALF 128
#define BATCH 512
#define THREADS 256
#define TANH3_A (-0.328685f)

typedef unsigned long long u64;
typedef ulonglong2 u64x2;

__device__ __forceinline__ u64 pk(float lo, float hi) {
    u64 r; asm("mov.b64 %0, {%1, %2};" : "=l"(r) : "f"(lo), "f"(hi)); return r;
}
__device__ __forceinline__ u64 fma2(u64 a, u64 b, u64 c) {
    u64 r; asm("fma.rn.f32x2 %0, %1, %2, %3;" : "=l"(r) : "l"(a), "l"(b), "l"(c)); return r;
}
__device__ __forceinline__ u64 add2(u64 a, u64 b) {
    u64 r; asm("add.rn.f32x2 %0, %1, %2;" : "=l"(r) : "l"(a), "l"(b)); return r;
}
__device__ __forceinline__ u64 sub2(u64 a, u64 b) {
    u64 r; asm("sub.rn.f32x2 %0, %1, %2;" : "=l"(r) : "l"(a), "l"(b)); return r;
}
__device__ __forceinline__ u64 mul2(u64 a, u64 b) {
    u64 r; asm("mul.rn.f32x2 %0, %1, %2;" : "=l"(r) : "l"(a), "l"(b)); return r;
}

// E-moment monomial tables: 34 = 4 singles + 10 pairs + 20 triples (row 4 of sEt = 1.0)
__device__ const int EM_A[34] = {0,1,2,3, 0,0,0,0,1,1,1,2,2,3,
    0,0,0,0,0,0,0,0,0,0, 1,1,1,1,1,1, 2,2,2, 3};
__device__ const int EM_B[34] = {4,4,4,4, 0,1,2,3,1,2,3,2,3,3,
    0,0,0,0,1,1,1,2,2,3, 1,1,1,2,2,3, 2,2,3, 3};
__device__ const int EM_C[34] = {4,4,4,4, 4,4,4,4,4,4,4,4,4,4,
    0,1,2,3,1,2,3,2,3,3, 1,2,3,2,3,3, 2,3,3, 3};
__device__ const float EM_CF[34] = {1,1,1,1, 1,1,1,1,1,1,1,1,1,1,
    1,3,3,3,3,6,6,3,6,3, 1,3,3,3,6,3, 1,3,3, 1};

__global__ void __launch_bounds__(THREADS, 2) enc_kernel(
    const float* __restrict__ ctx, const float* __restrict__ Wp,
    const float* __restrict__ bp, const float* __restrict__ Wr,
    const float* __restrict__ br, float* __restrict__ out)
{
    __shared__ float sEt[5][66];                       // E^T rows 0-3, row 4 = ones
    __shared__ __align__(16) u64 sEdup[NUM_ENT][4];    // pk(e,e)
    __shared__ __align__(16) u64 sWr2[5][64];
    __shared__ __align__(16) u64 sWp2[4][64];
    __shared__ u64 sBr2[64], sBp2[64];
    __shared__ u64 sEm[34];
    __shared__ __align__(16) u64 sIM[NUM_ENT][22];     // per-i D moments (dup)
    __shared__ __align__(16) u64 sHP[64][26];          // per-hp coefficients (row layout)

    const int tid = threadIdx.x;
    const int b = blockIdx.x;                          // ONE CTA PER BATCH

    // ---- Phase 0: stage inputs ----
    {
        const float ev = ctx[tid * BATCH + b];         // tid = j*4 + d
        sEt[tid & 3][tid >> 2] = ev;
        sEdup[tid >> 2][tid & 3] = pk(ev, ev);
        for (int k = tid; k < 5 * 64; k += THREADS) {
            const int d = k >> 6, hp = k & 63;
            sWr2[d][hp] = pk(Wr[d * HALF + 2 * hp], Wr[d * HALF + 2 * hp + 1]);
        }
        {
            const int d = tid >> 6, hp = tid & 63;
            sWp2[d][hp] = pk(Wp[d * HALF + 2 * hp], Wp[d * HALF + 2 * hp + 1]);
        }
        if (tid < 64) {
            sBr2[tid] = pk(br[2 * tid], br[2 * tid + 1]);
            sBp2[tid] = pk(bp[2 * tid], bp[2 * tid + 1]);
            sEt[4][tid] = 1.0f;
        }
    }
    __syncthreads();

    // ================= REGION A =================

    // A1: per-i D moments over ALL 64 i (4 threads per i, 16 j each, shfl-reduce)
    {
        const int i = tid >> 2;
        const int jb = (tid & 3) * 16;
        const float exi = sEt[0][i], eyi = sEt[1][i];
        float m[21];
#pragma unroll
        for (int k = 0; k < 21; k++) m[k] = 0.0f;
#pragma unroll
        for (int jj = 0; jj < 16; jj++) {
            const int j = jb + jj;
            const float e0 = sEt[0][j], e1 = sEt[1][j], e2 = sEt[2][j], e3 = sEt[3][j];
            const float dx = exi - e0, dy = eyi - e1;
            float d2 = fmaf(dx, dx, dy * dy);
            float d;
            if (i == j) { d = 1.0f; d2 = 1.0f; } else { d = sqrtf(d2); }
            const float d3 = d2 * d;
            const float de0 = d * e0, de1 = d * e1, de2 = d * e2, de3 = d * e3;
            m[0] += de0; m[1] += de1; m[2] += de2; m[3] += de3;             // D*E
            m[4] = fmaf(d2, e0, m[4]); m[5] = fmaf(d2, e1, m[5]);           // D^2*E
            m[6] = fmaf(d2, e2, m[6]); m[7] = fmaf(d2, e3, m[7]);
            m[8]  = fmaf(de0, e0, m[8]);  m[9]  = fmaf(de0, e1, m[9]);      // D*G
            m[10] = fmaf(de0, e2, m[10]); m[11] = fmaf(de0, e3, m[11]);
            m[12] = fmaf(de1, e1, m[12]); m[13] = fmaf(de1, e2, m[13]);
            m[14] = fmaf(de1, e3, m[14]); m[15] = fmaf(de2, e2, m[15]);
            m[16] = fmaf(de2, e3, m[16]); m[17] = fmaf(de3, e3, m[17]);
            m[18] += d; m[19] += d2; m[20] += d3;                           // D1,D2s,D3
        }
#pragma unroll
        for (int s = 1; s < 4; s <<= 1)
#pragma unroll
            for (int k = 0; k < 21; k++)
                m[k] += __shfl_xor_sync(0xffffffffu, m[k], s);
        if ((tid & 3) == 0) {
#pragma unroll
            for (int k = 0; k < 21; k++) sIM[i][k] = pk(m[k], m[k]);
            sIM[i][21] = 0;
        }
    }

    // A2: prop_emb (all threads, 16 i each; needs only sync0 data)
    {
        const int hp = tid & 63, ig = tid >> 6;
        const u64 wp0 = sWp2[0][hp], wp1 = sWp2[1][hp],
                  wp2v = sWp2[2][hp], wp3v = sWp2[3][hp];
        const u64 bp2v = sBp2[hp];
        const u64 ONE = pk(1.0f, 1.0f);
        const u64 T7 = pk(-0.053968254f, -0.053968254f);
        const u64 T5 = pk(0.13333334f, 0.13333334f);
        const u64 T3 = pk(-0.33333334f, -0.33333334f);
        float* outB = out + (size_t)b * NUM_ENT * 2 * HALF;
#pragma unroll 2
        for (int k = 0; k < 16; k++) {
            const int i = ig * 16 + k;
            const u64x2 eA = *reinterpret_cast<const u64x2*>(&sEdup[i][0]);
            const u64x2 eB = *reinterpret_cast<const u64x2*>(&sEdup[i][2]);
            u64 pp = fma2(eA.x, wp0, bp2v);
            pp = fma2(eA.y, wp1, pp);
            pp = fma2(eB.x, wp2v, pp);
            pp = fma2(eB.y, wp3v, pp);
            const u64 t = mul2(pp, pp);
            u64 u = fma2(t, T7, T5);
            u = fma2(t, u, T3);
            u = fma2(t, u, ONE);
            reinterpret_cast<u64*>(outB + (size_t)i * (2 * HALF))[hp] = mul2(pp, u);
        }
    }

    // A3: E-moment monomial sums, 136 threads (4 j-chunks of 16, shfl-reduce)
    if (tid < 136) {
        const int m = tid >> 2, c = tid & 3;
        const unsigned mask = (tid < 128) ? 0xffffffffu : 0xffu;
        const int a = EM_A[m], bb = EM_B[m], cc = EM_C[m];
        float s = 0.0f;
        const int j0 = c * 16;
#pragma unroll 4
        for (int jj = 0; jj < 16; jj++) {
            const int j = j0 + jj;
            s = fmaf(sEt[a][j] * sEt[bb][j], sEt[cc][j], s);
        }
        s += __shfl_xor_sync(mask, s, 1);
        s += __shfl_xor_sync(mask, s, 2);
        if (c == 0) { s *= EM_CF[m]; sEm[m] = pk(s, s); }
    }

    // A4: sEm-INDEPENDENT per-hp coefficients (threads 192..255)
    if (tid >= 192) {
        const int hp = tid - 192;
        const u64 w0 = sWr2[0][hp], w1 = sWr2[1][hp],
                  w2v = sWr2[2][hp], w3v = sWr2[3][hp], w = sWr2[4][hp];
        const u64 wq[4] = { w0, w1, w2v, w3v };
        u64 pr[10];
        pr[0] = mul2(w0, w0); pr[1] = mul2(w0, w1); pr[2] = mul2(w0, w2v);
        pr[3] = mul2(w0, w3v); pr[4] = mul2(w1, w1); pr[5] = mul2(w1, w2v);
        pr[6] = mul2(w1, w3v); pr[7] = mul2(w2v, w2v); pr[8] = mul2(w2v, w3v);
        pr[9] = mul2(w3v, w3v);
        u64 W2[10];
#pragma unroll
        for (int g = 0; g < 10; g++) W2[g] = pr[g];
        W2[1] = add2(W2[1], W2[1]); W2[2] = add2(W2[2], W2[2]);
        W2[3] = add2(W2[3], W2[3]); W2[5] = add2(W2[5], W2[5]);
        W2[6] = add2(W2[6], W2[6]); W2[8] = add2(W2[8], W2[8]);
        const u64 C3c = pk(3.0f, 3.0f);
        const u64 c3w = mul2(w, C3c);
        const u64 c3w2 = mul2(c3w, w);
        const u64 w3c = mul2(mul2(w, w), w);
        const u64 m6w = mul2(w, pk(-6.0f, -6.0f));
        const u64 nc3w2 = sub2(0ull, c3w2);
        u64* H = sHP[hp];
        H[2] = c3w;
        H[4] = c3w2;
        H[6] = w3c;
        H[7] = 0;
#pragma unroll
        for (int d = 0; d < 4; d++) H[8 + d] = mul2(wq[d], m6w);     // u
#pragma unroll
        for (int d = 0; d < 4; d++) H[12 + d] = mul2(wq[d], nc3w2);  // t
#pragma unroll
        for (int g = 0; g < 10; g++) H[16 + g] = mul2(W2[g], c3w);   // v
    }
    __syncthreads();

    // ---- Phase S: sEm-DEPENDENT coefficients (128 threads) ----
    if (tid < 64) {
        const int hp = tid;
        const u64 w0 = sWr2[0][hp], w1 = sWr2[1][hp],
                  w2v = sWr2[2][hp], w3v = sWr2[3][hp], w = sWr2[4][hp];
        u64 S1 = mul2(sEm[0], w0);
        S1 = fma2(sEm[1], w1, S1);
        S1 = fma2(sEm[2], w2v, S1);
        S1 = fma2(sEm[3], w3v, S1);
        u64 pr[10];
        pr[0] = mul2(w0, w0); pr[1] = mul2(w0, w1); pr[2] = mul2(w0, w2v);
        pr[3] = mul2(w0, w3v); pr[4] = mul2(w1, w1); pr[5] = mul2(w1, w2v);
        pr[6] = mul2(w1, w3v); pr[7] = mul2(w2v, w2v); pr[8] = mul2(w2v, w3v);
        pr[9] = mul2(w3v, w3v);
        u64 W2[10];
#pragma unroll
        for (int g = 0; g < 10; g++) W2[g] = pr[g];
        W2[1] = add2(W2[1], W2[1]); W2[2] = add2(W2[2], W2[2]);
        W2[3] = add2(W2[3], W2[3]); W2[5] = add2(W2[5], W2[5]);
        W2[6] = add2(W2[6], W2[6]); W2[8] = add2(W2[8], W2[8]);
        u64 S2 = mul2(sEm[4], W2[0]);
#pragma unroll
        for (int g = 1; g < 10; g++) S2 = fma2(sEm[4 + g], W2[g], S2);
        const u64 z = add2(w, sBr2[hp]);
        sHP[hp][0] = sub2(sub2(0ull, S1), z);          // Lc
        sHP[hp][1] = mul2(S1, pk(-3.0f, -3.0f));       // n3S1
        sHP[hp][3] = mul2(S2, pk(3.0f, 3.0f));         // p3S2
    } else if (tid < 128) {
        const int hp = tid - 64;
        const u64 w0 = sWr2[0][hp], w1 = sWr2[1][hp],
                  w2v = sWr2[2][hp], w3v = sWr2[3][hp], w = sWr2[4][hp];
        const u64 wq[4] = { w0, w1, w2v, w3v };
        u64 pr[10];
        pr[0] = mul2(w0, w0); pr[1] = mul2(w0, w1); pr[2] = mul2(w0, w2v);
        pr[3] = mul2(w0, w3v); pr[4] = mul2(w1, w1); pr[5] = mul2(w1, w2v);
        pr[6] = mul2(w1, w3v); pr[7] = mul2(w2v, w2v); pr[8] = mul2(w2v, w3v);
        pr[9] = mul2(w3v, w3v);
        constexpr int P3[20] = {0,0,0,0,1,1,1,2,2,3,4,4,4,5,5,6,7,7,8,9};
        constexpr int C3i[20] = {0,1,2,3,1,2,3,2,3,3,1,2,3,2,3,3,2,3,3,3};
        u64 S3 = 0;
#pragma unroll
        for (int m3 = 0; m3 < 20; m3++)
            S3 = fma2(sEm[14 + m3], mul2(pr[P3[m3]], wq[C3i[m3]]), S3);
        const u64 z = add2(w, sBr2[hp]);
        const u64 z3 = mul2(z, mul2(z, z));
        sHP[hp][5] = sub2(sub2(0ull, S3), z3);         // K0
    }
    __syncthreads();

    // ---- Epilogue: thread = (hp, ig); 16 i each; FULL coefficient hoist ----
    {
        const int hp = tid & 63;
        const int ig = tid >> 6;

        const u64 wr0 = sWr2[0][hp], wr1 = sWr2[1][hp],
                  wr2v = sWr2[2][hp], wr3v = sWr2[3][hp], wr4 = sWr2[4][hp];
        const u64 br2v = sBr2[hp];

        const u64x2* Hx = reinterpret_cast<const u64x2*>(sHP[hp]);
        const u64x2 h01 = Hx[0], h23 = Hx[1], h45 = Hx[2], h6_ = Hx[3];
        const u64 Lc = h01.x, n3S1 = h01.y, c3w = h23.x, p3S2 = h23.y;
        const u64 c3w2 = h45.x, K0 = h45.y, w3c = h6_.x;
        const u64x2 u01 = Hx[4], u23 = Hx[5], t01 = Hx[6], t23 = Hx[7];
        const u64x2 v01 = Hx[8], v23 = Hx[9], v45 = Hx[10], v67 = Hx[11], v89 = Hx[12];

        const u64 A2 = pk(TANH3_A, TANH3_A);
        const u64 C64 = pk(64.0f, 64.0f);

        float* outB = out + (size_t)b * NUM_ENT * 2 * HALF;

#pragma unroll 2
        for (int k = 0; k < 16; k++) {
            const int i = ig * 16 + k;
            const u64x2 eA = *reinterpret_cast<const u64x2*>(&sEdup[i][0]);
            const u64x2 eB = *reinterpret_cast<const u64x2*>(&sEdup[i][2]);

            u64 p = mul2(eA.x, wr0);
            p = fma2(eA.y, wr1, p);
            p = fma2(eB.x, wr2v, p);
            p = fma2(eB.y, wr3v, p);
            const u64 q = add2(p, br2v);

            const u64x2* M = reinterpret_cast<const u64x2*>(sIM[i]);  // broadcast
            const u64x2 de01 = M[0], de23 = M[1], f01 = M[2], f23 = M[3];
            const u64x2 g01 = M[4], g23 = M[5], g45 = M[6], g67 = M[7], g89 = M[8];
            const u64x2 dd01 = M[9], dd2_ = M[10];   // D1,D2s | D3,pad

            const u64 C2 = fma2(dd01.x, c3w, n3S1);

            u64 C1 = fma2(de01.x, u01.x, p3S2);
            C1 = fma2(de01.y, u01.y, C1);
            C1 = fma2(de23.x, u23.x, C1);
            C1 = fma2(de23.y, u23.y, C1);
            C1 = fma2(dd01.y, c3w2, C1);

            u64 C0 = fma2(g01.x, v01.x, K0);
            C0 = fma2(g01.y, v01.y, C0);
            C0 = fma2(g23.x, v23.x, C0);
            C0 = fma2(g23.y, v23.y, C0);
            C0 = fma2(g45.x, v45.x, C0);
            C0 = fma2(g45.y, v45.y, C0);
            C0 = fma2(g67.x, v67.x, C0);
            C0 = fma2(g67.y, v67.y, C0);
            C0 = fma2(g89.x, v89.x, C0);
            C0 = fma2(g89.y, v89.y, C0);
            C0 = fma2(f01.x, t01.x, C0);
            C0 = fma2(f01.y, t01.y, C0);
            C0 = fma2(f23.x, t23.x, C0);
            C0 = fma2(f23.y, t23.y, C0);
            C0 = fma2(dd2_.x, w3c, C0);

            u64 cub = fma2(C64, q, C2);
            cub = fma2(cub, q, C1);
            cub = fma2(cub, q, C0);

            u64 lin = fma2(C64, q, Lc);
            lin = fma2(dd01.x, wr4, lin);

            const u64 res = fma2(A2, cub, lin);
            reinterpret_cast<u64*>(outB + (size_t)i * (2 * HALF))[64 + hp] = res;
        }
    }
}

extern "C" void kernel_launch(void* const* d_in, const int* in_sizes, int n_in,
                              void* d_out, int out_size) {
    const float* ctx = (const float*)d_in[0];
    const float* Wp  = (const float*)d_in[1];
    const float* bp  = (const float*)d_in[2];
    const float* Wr  = (const float*)d_in[3];
    const float* br  = (const float*)d_in[4];
    float* out = (float*)d_out;
    (void)in_sizes; (void)n_in; (void)out_size;
    enc_kernel<<<BATCH, THREADS>>>(ctx, Wp, bp, Wr, br, out);
}